// round 2
// baseline (speedup 1.0000x reference)
#include <cuda_runtime.h>

#define DD 48
#define HH 256
#define WW 256
#define HM 128
#define WM 128
#define PHN 4

// Pair table: for each voxel (z,y,x): (c0[x], c1[x], c0[x+1], c1[x+1]) with x+1 clamped.
// 48*256*256 * 16B = 50.3 MB device scratch (static, allowed).
__device__ float4 g_pairs[DD * HH * WW];

// ---------------------------------------------------------------------------
// Build pair table (streaming, ~75MB traffic)
// ---------------------------------------------------------------------------
__global__ __launch_bounds__(256) void build_pairs_kernel(const float2* __restrict__ img)
{
    int i = blockIdx.x * blockDim.x + threadIdx.x;
    if (i >= DD * HH * WW) return;
    int x = i & (WW - 1);
    float2 a = img[i];
    float2 b = img[(x < WW - 1) ? i + 1 : i];
    g_pairs[i] = make_float4(a.x, a.y, b.x, b.y);
}

// ---------------------------------------------------------------------------
// Channel-0 passthrough copy
// ---------------------------------------------------------------------------
__global__ __launch_bounds__(256) void copy_img_kernel(
    const float4* __restrict__ in, float4* __restrict__ out, int n4)
{
    int i = blockIdx.x * blockDim.x + threadIdx.x;
    if (i < n4) out[i] = in[i];
}

// ---------------------------------------------------------------------------
// Trilinear sample of the pair table: returns both channels.
// ---------------------------------------------------------------------------
__device__ __forceinline__ float2 sample_img(float cz, float cy, float cx)
{
    float zf = floorf(cz), yf = floorf(cy), xf = floorf(cx);
    int zi = (int)zf, yi = (int)yf, xi = (int)xf;
    float wz = cz - zf, wy = cy - yf, wx = cx - xf;

    // x handling via pair table: entry at xc covers columns (xc, xc+1)
    int  xc  = min(max(xi, 0), WW - 2);
    int  off = xi - xc;                       // <0: xi left of entry; >0: right
    bool v0x = ((unsigned)xi < (unsigned)WW);
    bool v1x = ((unsigned)(xi + 1) < (unsigned)WW);
    float wx0 = v0x ? (1.0f - wx) : 0.0f;     // weight for column xi
    float wx1 = v1x ? wx : 0.0f;              // weight for column xi+1
    bool hi0 = (off > 0);                     // corner xi lives in .zw half
    bool lo1 = (off < 0);                     // corner xi+1 lives in .xy half

    float acc0 = 0.0f, acc1 = 0.0f;
    #pragma unroll
    for (int dz = 0; dz < 2; ++dz) {
        int zz = zi + dz;
        float wzv = dz ? wz : (1.0f - wz);
        int  zc = min(max(zz, 0), DD - 1);
        bool zok = ((unsigned)zz < (unsigned)DD);
        #pragma unroll
        for (int dy = 0; dy < 2; ++dy) {
            int yy = yi + dy;
            float wyv = dy ? wy : (1.0f - wy);
            int  yc = min(max(yy, 0), HH - 1);
            bool yok = ((unsigned)yy < (unsigned)HH);
            float wb = (zok && yok) ? (wzv * wyv) : 0.0f;

            float4 v = __ldg(&g_pairs[(zc * HH + yc) * WW + xc]);
            float c0x = hi0 ? v.z : v.x;
            float c0y = hi0 ? v.w : v.y;
            float c1x = lo1 ? v.x : v.z;
            float c1y = lo1 ? v.y : v.w;

            float w0 = wb * wx0;
            float w1 = wb * wx1;
            acc0 += w0 * c0x + w1 * c1x;
            acc1 += w0 * c0y + w1 * c1y;
        }
    }
    return make_float2(acc0, acc1);
}

// ---------------------------------------------------------------------------
// Fused upsample+warp. Block = one (p,z,y) row; 128 threads x 2 pixels.
// ---------------------------------------------------------------------------
__global__ __launch_bounds__(128) void mvf_warp_kernel(
    const float* __restrict__ mvf,     // [PHN][3][DD][HM][WM]
    float* __restrict__ out)           // [5][DD][HH][WW][2]
{
    const int t = threadIdx.x;      // 0..127  -> pixels x = 2t, 2t+1
    const int y = blockIdx.x;       // 0..255
    const int z = blockIdx.y;       // 0..47
    const int p = blockIdx.z;       // 0..3

    // ---- y interpolation factors (shared by both pixels) ----
    float fy = fminf(fmaxf(y * 0.5f - 0.25f, 0.0f), (float)(HM - 1));
    int   y0 = (int)fy;
    float wy = fy - (float)y0;
    int   y1 = min(y0 + 1, HM - 1);

    // ---- x: pixel A (x=2t) taps cols {cm,c0}; pixel B (x=2t+1) taps {c0,cp} ----
    float fxA = fmaxf((float)t - 0.25f, 0.0f);
    int   cm  = (int)fxA;                 // = max(t-1,0)
    float wxA = fxA - (float)cm;          // 0.75 (t>=1) or 0 (t=0)
    float fxB = fminf((float)t + 0.25f, (float)(WM - 1));
    float wxB = fxB - (float)t;           // 0.25 (t<=126) or 0 (t=127)
    int   c0  = t;
    int   cp  = min(t + 1, WM - 1);

    const int mbase = ((p * 3) * DD + z) * (HM * WM);
    const int cstr  = DD * HM * WM;

    float mA[3], mB[3];
    #pragma unroll
    for (int c = 0; c < 3; ++c) {
        const float* r0 = mvf + mbase + c * cstr + y0 * WM;
        const float* r1 = mvf + mbase + c * cstr + y1 * WM;
        float vm0 = __ldg(r0 + cm), v00 = __ldg(r0 + c0), vp0 = __ldg(r0 + cp);
        float vm1 = __ldg(r1 + cm), v01 = __ldg(r1 + c0), vp1 = __ldg(r1 + cp);
        float a0 = vm0 + wxA * (v00 - vm0);
        float a1 = vm1 + wxA * (v01 - vm1);
        float b0 = v00 + wxB * (vp0 - v00);
        float b1 = v01 + wxB * (vp1 - v01);
        mA[c] = a0 + wy * (a1 - a0);
        mB[c] = b0 + wy * (b1 - b0);
    }

    float2 rA = sample_img((float)z + mA[0],
                           (float)y + 2.0f * mA[1],
                           (float)(2 * t) + 2.0f * mA[2]);
    float2 rB = sample_img((float)z + mB[0],
                           (float)y + 2.0f * mB[1],
                           (float)(2 * t + 1) + 2.0f * mB[2]);

    float4* o = (float4*)(out + ((((1 + p) * DD + z) * HH + y) * WW) * 2) + t;
    *o = make_float4(rA.x, rA.y, rB.x, rB.y);
}

extern "C" void kernel_launch(void* const* d_in, const int* in_sizes, int n_in,
                              void* d_out, int out_size)
{
    const float* image = (const float*)d_in[0];   // 6291456 floats
    const float* mvf   = (const float*)d_in[1];   // 9437184 floats
    float* out = (float*)d_out;                   // 31457280 floats

    // channel 0: straight copy of the input image
    const int n4 = (DD * HH * WW * 2) / 4;
    copy_img_kernel<<<(n4 + 255) / 256, 256>>>((const float4*)image, (float4*)out, n4);

    // build pair table
    const int npx = DD * HH * WW;
    build_pairs_kernel<<<(npx + 255) / 256, 256>>>((const float2*)image);

    // channels 1..4: fused upsample + warp (reads pair table)
    dim3 grid(HH, DD, PHN);
    mvf_warp_kernel<<<grid, 128>>>(mvf, out);
}